// round 15
// baseline (speedup 1.0000x reference)
#include <cuda_runtime.h>
#include <cuda_bf16.h>
#include <cuda_fp16.h>
#include <math.h>
#include <stdint.h>

#define N_NODES 100000
#define NNZ     1000000
#define F_IN    1433
#define F_HID   128
#define F_OUTD  64
#define N_EDGES 40000
#define EPSV    1e-6f
#define KPAD0   1440
#define SCAN_BLK 1024
#define NBLK_SCAN ((N_NODES + SCAN_BLK - 1) / SCAN_BLK)   // 98

// -------- static device scratch --------
__device__ __half g_supporth[(size_t)N_NODES * F_HID];    // fp16 GEMM output
__device__ __half g_xh[(size_t)N_NODES * F_HID];          // fp16 x (pre-pairnorm, layers 0-1)
__device__ float g_x[(size_t)N_NODES * F_HID];            // fp32 x (layer 2, pre-pairnorm)
__device__ float g_colsum3[3][F_HID];
__device__ __half g_W0h[(size_t)128 * KPAD0];
__device__ __half g_W1h[(size_t)128 * F_HID];
__device__ __half g_W2h[(size_t)128 * F_HID];
// CSR
__device__ int  g_rowcnt[N_NODES];
__device__ int  g_rowoff[N_NODES + 1];
__device__ int  g_blksum[128];
__device__ int2 g_epack[NNZ];

__device__ __forceinline__ unsigned pack2h(float f0, float f1) {
    unsigned r;
    asm("cvt.rn.f16x2.f32 %0, %1, %2;" : "=r"(r) : "f"(f1), "f"(f0));
    return r;   // low half = f0
}

// ================= prep: zero colsums, convert all W to fp16 transposed =================
#define U0 (128 * (KPAD0 / 8))        // 23040
#define U12 (128 * (F_HID / 8))       // 2048
#define PREP_BASE 512
#define PREP_TOTAL (PREP_BASE + U0 + 2 * U12)

__global__ void prep_kernel(const float* __restrict__ W0, const float* __restrict__ W1,
                            const float* __restrict__ W2) {
    int t = blockIdx.x * blockDim.x + threadIdx.x;
    if (t < 384) { ((float*)g_colsum3)[t] = 0.f; return; }
    if (t < PREP_BASE) return;
    int u = t - PREP_BASE;
    if (u < U0) {
        int n = u / (KPAD0 / 8);
        int k0 = (u - n * (KPAD0 / 8)) << 3;
        __half hh[8];
#pragma unroll
        for (int e = 0; e < 8; e++) {
            int k = k0 + e;
            hh[e] = __float2half_rn((k < F_IN) ? __ldg(&W0[(size_t)k * 128 + n]) : 0.f);
        }
        *(uint4*)&g_W0h[(size_t)n * KPAD0 + k0] = *(uint4*)hh;
    } else if (u < U0 + U12) {
        int v = u - U0;
        int n = v >> 4;
        int k0 = (v & 15) << 3;
        __half hh[8];
#pragma unroll
        for (int e = 0; e < 8; e++)
            hh[e] = __float2half_rn(__ldg(&W1[(size_t)(k0 + e) * 128 + n]));
        *(uint4*)&g_W1h[(size_t)n * F_HID + k0] = *(uint4*)hh;
    } else if (u < U0 + 2 * U12) {
        int v = u - U0 - U12;
        int n = v >> 4;
        int k0 = (v & 15) << 3;
        __half hh[8];
#pragma unroll
        for (int e = 0; e < 8; e++)
            hh[e] = __float2half_rn((n < F_OUTD) ? __ldg(&W2[(size_t)(k0 + e) * F_OUTD + n]) : 0.f);
        *(uint4*)&g_W2h[(size_t)n * F_HID + k0] = *(uint4*)hh;
    }
}

// ================= CSR build =================
__global__ void csr_zero_kernel() {
    int i = blockIdx.x * blockDim.x + threadIdx.x;
    if (i < N_NODES) g_rowcnt[i] = 0;
}
__global__ void csr_hist_kernel(const int* __restrict__ row) {
    int e = blockIdx.x * blockDim.x + threadIdx.x;
    if (e < NNZ) atomicAdd(&g_rowcnt[row[e]], 1);
}
__global__ __launch_bounds__(SCAN_BLK) void csr_scanA_kernel() {
    __shared__ int sm[SCAN_BLK];
    int t = threadIdx.x;
    int i = blockIdx.x * SCAN_BLK + t;
    int v = (i < N_NODES) ? g_rowcnt[i] : 0;
    sm[t] = v;
    __syncthreads();
#pragma unroll
    for (int s = 1; s < SCAN_BLK; s <<= 1) {
        int a = (t >= s) ? sm[t - s] : 0;
        __syncthreads();
        sm[t] += a;
        __syncthreads();
    }
    if (i < N_NODES) g_rowoff[i] = sm[t] - v;
    if (t == SCAN_BLK - 1) g_blksum[blockIdx.x] = sm[t];
}
__global__ void csr_scanB_kernel() {
    __shared__ int sm[128];
    int t = threadIdx.x;
    int v = (t < NBLK_SCAN) ? g_blksum[t] : 0;
    sm[t] = v;
    __syncthreads();
#pragma unroll
    for (int s = 1; s < 128; s <<= 1) {
        int a = (t >= s) ? sm[t - s] : 0;
        __syncthreads();
        sm[t] += a;
        __syncthreads();
    }
    g_blksum[t] = sm[t] - v;
}
__global__ void csr_scanC_kernel() {
    int i = blockIdx.x * blockDim.x + threadIdx.x;
    if (i < N_NODES) {
        g_rowoff[i] += g_blksum[i >> 10];
        g_rowcnt[i] = 0;
    }
    if (i == 0) g_rowoff[N_NODES] = NNZ;
}
__global__ void csr_scatter_kernel(const int* __restrict__ row, const int* __restrict__ col,
                                   const float* __restrict__ val) {
    int e = blockIdx.x * blockDim.x + threadIdx.x;
    if (e >= NNZ) return;
    int r = row[e];
    int p = g_rowoff[r] + atomicAdd(&g_rowcnt[r], 1);
    g_epack[p] = make_int2(col[e], __float_as_int(val[e]));
}

// ============ shared GEMM helpers ============
#define BM 128
#define BK 32
#define BKP 40
#define PLANE_BYTES (128 * BKP * 2)          // 10240
#define OFF_A  0
#define OFF_B  (PLANE_BYTES)
#define STAGE_BYTES (2 * PLANE_BYTES)        // 20480
#define GEMM_SMEM (2 * STAGE_BYTES)          // 40960 (layer-0 kernel)

__device__ __forceinline__ void mma16816h(float c[4], const unsigned a[4], const unsigned* b) {
    asm volatile(
        "mma.sync.aligned.m16n8k16.row.col.f32.f16.f16.f32 "
        "{%0,%1,%2,%3}, {%4,%5,%6,%7}, {%8,%9}, {%0,%1,%2,%3};"
        : "+f"(c[0]), "+f"(c[1]), "+f"(c[2]), "+f"(c[3])
        : "r"(a[0]), "r"(a[1]), "r"(a[2]), "r"(a[3]), "r"(b[0]), "r"(b[1]));
}
__device__ __forceinline__ void ldmx4(unsigned r[4], uint32_t addr) {
    asm volatile("ldmatrix.sync.aligned.m8n8.x4.shared.b16 {%0,%1,%2,%3}, [%4];"
                 : "=r"(r[0]), "=r"(r[1]), "=r"(r[2]), "=r"(r[3]) : "r"(addr));
}
__device__ __forceinline__ void cp_async16(uint32_t dst, const void* src, bool ok) {
    int bytes = ok ? 16 : 0;
    asm volatile("cp.async.cg.shared.global [%0], [%1], 16, %2;"
                 :: "r"(dst), "l"(src), "r"(bytes));
}

// ============ layer-0 GEMM: A fp32 -> fp16 in-kernel, double-buffered ============
__global__ __launch_bounds__(256, 2) void gemm0_kernel(
    const float* __restrict__ A, const __half* __restrict__ Wh,
    __half* __restrict__ C, int M, int K, int Kpad)
{
    extern __shared__ __align__(16) char dynsmem[];
    const uint32_t sbase = (uint32_t)__cvta_generic_to_shared(dynsmem);

    const int tid  = threadIdx.x;
    const int wid  = tid >> 5;
    const int lane = tid & 31;
    const int bm   = blockIdx.y * BM;
    const int g    = lane >> 2;
    const int qt   = lane & 3;
    const int warp_m = (wid >> 1) * 32;
    const int warp_n = (wid & 1) * 64;

    const int rA0 = warp_m + (lane & 7) + (lane & 8);
    const int cA  = (lane & 16) >> 1;
    const int rB0 = warp_n + (lane & 7) + ((lane & 16) >> 1);
    const int cB  = (lane & 8);

    float acc[2][8][4];
#pragma unroll
    for (int mi = 0; mi < 2; mi++)
#pragma unroll
        for (int ni = 0; ni < 8; ni++)
#pragma unroll
            for (int q = 0; q < 4; q++) acc[mi][ni][q] = 0.f;

    float pv[2][8];

    auto issue_B = [&](int stage, int k0) {
        uint32_t sb = sbase + stage * STAGE_BYTES;
#pragma unroll
        for (int p = 0; p < 2; p++) {
            int c = tid + p * 256;
            int row = c >> 2;
            int off = (c & 3) << 3;
            cp_async16(sb + OFF_B + row * (BKP * 2) + off * 2,
                       &Wh[(size_t)row * KPAD0 + k0 + off], true);
        }
    };
    auto prefetch_A = [&](int k0) {
        bool full = (k0 + BK <= K);
#pragma unroll
        for (int u2 = 0; u2 < 2; u2++) {
            int u = tid + u2 * 256;
            int r = u >> 2;
            int o = (u & 3) << 3;
            int m = bm + r;
            bool mok = m < M;
            const float* Ar = A + (size_t)m * K + k0 + o;
            if (full) {
#pragma unroll
                for (int e = 0; e < 8; e++) pv[u2][e] = mok ? __ldg(Ar + e) : 0.f;
            } else {
#pragma unroll
                for (int e = 0; e < 8; e++) {
                    int k = k0 + o + e;
                    pv[u2][e] = (mok && k < K) ? __ldg(Ar + e) : 0.f;
                }
            }
        }
    };
    auto cvt_sts_A = [&](int stage) {
#pragma unroll
        for (int u2 = 0; u2 < 2; u2++) {
            int u = tid + u2 * 256;
            int r = u >> 2;
            int o = (u & 3) << 3;
            unsigned ph[4];
#pragma unroll
            for (int p = 0; p < 4; p++)
                ph[p] = pack2h(pv[u2][2 * p], pv[u2][2 * p + 1]);
            *(uint4*)(dynsmem + stage * STAGE_BYTES + OFF_A + r * (BKP * 2) + o * 2) =
                make_uint4(ph[0], ph[1], ph[2], ph[3]);
        }
    };

    const int nt = Kpad / BK;
    prefetch_A(0);
    cvt_sts_A(0);
    issue_B(0, 0);
    asm volatile("cp.async.commit_group;" ::: "memory");

    for (int kt = 0; kt < nt; kt++) {
        int cur = kt & 1;
        int nxt = cur ^ 1;
        asm volatile("cp.async.wait_group 0;" ::: "memory");
        __syncthreads();

        bool hn = (kt + 1) < nt;
        int k1 = (kt + 1) * BK;
        if (hn) {
            prefetch_A(k1);
            issue_B(nxt, k1);
        }
        asm volatile("cp.async.commit_group;" ::: "memory");

        uint32_t sA = sbase + cur * STAGE_BYTES;
#pragma unroll
        for (int kh = 0; kh < BK; kh += 16) {
            unsigned a[2][4];
#pragma unroll
            for (int mi = 0; mi < 2; mi++) {
                uint32_t ra = sA + OFF_A + (rA0 + mi * 16) * (BKP * 2) + (cA + kh) * 2;
                ldmx4(a[mi], ra);
            }
#pragma unroll
            for (int nip = 0; nip < 4; nip++) {
                unsigned b4[4];
                uint32_t rb = sA + OFF_B + (rB0 + nip * 16) * (BKP * 2) + (cB + kh) * 2;
                ldmx4(b4, rb);
#pragma unroll
                for (int mi = 0; mi < 2; mi++) {
                    mma16816h(acc[mi][2 * nip],     a[mi], &b4[0]);
                    mma16816h(acc[mi][2 * nip + 1], a[mi], &b4[2]);
                }
            }
        }

        if (hn) cvt_sts_A(nxt);
    }

#pragma unroll
    for (int mi = 0; mi < 2; mi++) {
#pragma unroll
        for (int ni = 0; ni < 8; ni++) {
            int row0 = bm + warp_m + mi * 16 + g;
            int col  = warp_n + ni * 8 + 2 * qt;
            if (row0 < M)
                *(unsigned*)&C[(size_t)row0 * F_HID + col] =
                    pack2h(acc[mi][ni][0], acc[mi][ni][1]);
            if (row0 + 8 < M)
                *(unsigned*)&C[(size_t)(row0 + 8) * F_HID + col] =
                    pack2h(acc[mi][ni][2], acc[mi][ni][3]);
        }
    }
}

// ============ layers 1-2: fused PairNorm + GEMM (K=128 fixed) ============
// A loader reads raw fp16 g_xh, applies PN-SI (colsum mean + per-row L2), stores
// all 4 k-stage A tiles; W via cp.async all stages; single sync; no double buffer.
#define PN_A_ST(kt) ((kt) * PLANE_BYTES)                // 4 x 10240
#define PN_B_BASE   (4 * PLANE_BYTES)                   // 40960

template <int BNT>
__global__ __launch_bounds__(256, 2) void gemm_pn_kernel(
    const __half* __restrict__ Xh, const float* __restrict__ colsum,
    const __half* __restrict__ Wh, __half* __restrict__ C, int M, int N)
{
    constexpr int NN = BNT / 16;
    constexpr int B_STAGE = BNT * (BKP * 2) / 2;        // BNT*40 bytes? no: BNT rows x 80B
    constexpr int B_ST_BYTES = BNT * (BKP * 2);         // rows * 80
    extern __shared__ __align__(16) char dynsmem[];
    const uint32_t sbase = (uint32_t)__cvta_generic_to_shared(dynsmem);
    (void)B_STAGE;

    const int tid  = threadIdx.x;
    const int wid  = tid >> 5;
    const int lane = tid & 31;
    const int bm   = blockIdx.y * BM;
    const int g    = lane >> 2;
    const int qt   = lane & 3;
    const int warp_m = (wid >> 1) * 32;
    const int warp_n = (wid & 1) * (BNT / 2);

    const int rA0 = warp_m + (lane & 7) + (lane & 8);
    const int cA  = (lane & 16) >> 1;
    const int rB0 = warp_n + (lane & 7) + ((lane & 16) >> 1);
    const int cB  = (lane & 8);

    // ---- B: cp.async all 4 k-stages ----
#pragma unroll
    for (int kt = 0; kt < 4; kt++) {
#pragma unroll
        for (int p = 0; p < BNT / 64; p++) {
            int c = tid + p * 256;
            int row = c >> 2;
            int off = (c & 3) << 3;
            cp_async16(sbase + PN_B_BASE + kt * B_ST_BYTES + row * (BKP * 2) + off * 2,
                       &Wh[(size_t)row * F_HID + kt * 32 + off], true);
        }
    }
    asm volatile("cp.async.commit_group;" ::: "memory");

    // ---- A: load + PairNorm + store (each thread owns 32 elems of a row, 4 threads/row) ----
    const float invN = 1.0f / N_NODES;
#pragma unroll
    for (int p = 0; p < 2; p++) {
        int c = tid + p * 256;
        int r = c >> 2;        // 0..127
        int q = c & 3;         // quarter within row
        int m = bm + r;
        int ms = (m < M) ? m : 0;
        float v[32];
        float ss = 0.f;
#pragma unroll
        for (int kt = 0; kt < 4; kt++) {
            int f0 = kt * 32 + q * 8;
            uint4 u = *(const uint4*)&Xh[(size_t)ms * F_HID + f0];
            float4 mA = *(const float4*)&colsum[f0];
            float4 mB = *(const float4*)&colsum[f0 + 4];
            float2 a0 = __half22float2(*(__half2*)&u.x);
            float2 a1 = __half22float2(*(__half2*)&u.y);
            float2 a2 = __half22float2(*(__half2*)&u.z);
            float2 a3 = __half22float2(*(__half2*)&u.w);
            float* vv = &v[kt * 8];
            vv[0] = a0.x - mA.x * invN; vv[1] = a0.y - mA.y * invN;
            vv[2] = a1.x - mA.z * invN; vv[3] = a1.y - mA.w * invN;
            vv[4] = a2.x - mB.x * invN; vv[5] = a2.y - mB.y * invN;
            vv[6] = a3.x - mB.z * invN; vv[7] = a3.y - mB.w * invN;
#pragma unroll
            for (int e = 0; e < 8; e++) ss += vv[e] * vv[e];
        }
        // reduce ss across the 4-lane row group
        ss += __shfl_xor_sync(0xffffffffu, ss, 1);
        ss += __shfl_xor_sync(0xffffffffu, ss, 2);
        float inv = rsqrtf(EPSV + ss);
#pragma unroll
        for (int kt = 0; kt < 4; kt++) {
            float* vv = &v[kt * 8];
            unsigned ph[4];
#pragma unroll
            for (int e = 0; e < 4; e++)
                ph[e] = pack2h(vv[2 * e] * inv, vv[2 * e + 1] * inv);
            *(uint4*)(dynsmem + PN_A_ST(kt) + r * (BKP * 2) + q * 16) =
                make_uint4(ph[0], ph[1], ph[2], ph[3]);
        }
    }

    asm volatile("cp.async.wait_group 0;" ::: "memory");
    __syncthreads();

    // ---- compute all 4 k-stages ----
    float acc[2][NN][4];
#pragma unroll
    for (int mi = 0; mi < 2; mi++)
#pragma unroll
        for (int ni = 0; ni < NN; ni++)
#pragma unroll
            for (int q = 0; q < 4; q++) acc[mi][ni][q] = 0.f;

#pragma unroll
    for (int kt = 0; kt < 4; kt++) {
        uint32_t sA = sbase + PN_A_ST(kt);
        uint32_t sB = sbase + PN_B_BASE + kt * B_ST_BYTES;
#pragma unroll
        for (int kh = 0; kh < 32; kh += 16) {
            unsigned a[2][4];
#pragma unroll
            for (int mi = 0; mi < 2; mi++)
                ldmx4(a[mi], sA + (rA0 + mi * 16) * (BKP * 2) + (cA + kh) * 2);
#pragma unroll
            for (int nip = 0; nip < NN / 2; nip++) {
                unsigned b4[4];
                ldmx4(b4, sB + (rB0 + nip * 16) * (BKP * 2) + (cB + kh) * 2);
#pragma unroll
                for (int mi = 0; mi < 2; mi++) {
                    mma16816h(acc[mi][2 * nip],     a[mi], &b4[0]);
                    mma16816h(acc[mi][2 * nip + 1], a[mi], &b4[2]);
                }
            }
        }
    }

    // ---- fp16 epilogue ----
#pragma unroll
    for (int mi = 0; mi < 2; mi++) {
#pragma unroll
        for (int ni = 0; ni < NN; ni++) {
            int row0 = bm + warp_m + mi * 16 + g;
            int col  = warp_n + ni * 8 + 2 * qt;
            if (col < N) {
                if (row0 < M)
                    *(unsigned*)&C[(size_t)row0 * N + col] =
                        pack2h(acc[mi][ni][0], acc[mi][ni][1]);
                if (row0 + 8 < M)
                    *(unsigned*)&C[(size_t)(row0 + 8) * N + col] =
                        pack2h(acc[mi][ni][2], acc[mi][ni][3]);
            }
        }
    }
}
#define PN_SMEM_128 (PN_B_BASE + 4 * 128 * (BKP * 2))   // 40960 + 40960 = 81920
#define PN_SMEM_64  (PN_B_BASE + 4 * 64 * (BKP * 2))    // 40960 + 20480 = 61440

// ======== fused CSR-gather SpMM (fp16 support) + bias + ReLU + colsum ========
#define RPW 2
template <int FV, int HOUT>
__global__ __launch_bounds__(256) void spmm_fused_kernel(const float* __restrict__ bias,
                                                         float* __restrict__ colsum) {
    constexpr int VEC = FV / 32;
    __shared__ float cs[FV];
    int tid = threadIdx.x;
    if (tid < FV) cs[tid] = 0.f;
    __syncthreads();
    int lane = tid & 31;
    int warp = (((int)blockIdx.x * blockDim.x) + tid) >> 5;
    int r0 = warp * RPW;

    float bv[VEC], bsum[VEC];
#pragma unroll
    for (int v = 0; v < VEC; v++) {
        bv[v] = bias[lane * VEC + v];
        bsum[v] = 0.f;
    }

    if (r0 < N_NODES) {
        for (int rr = 0; rr < RPW; rr++) {
            int r = r0 + rr;
            if (r >= N_NODES) break;
            int beg = __ldg(&g_rowoff[r]);
            int end = __ldg(&g_rowoff[r + 1]);
            float acc[VEC];
#pragma unroll
            for (int v = 0; v < VEC; v++) acc[v] = 0.f;

            auto gather = [&](int2 p) {
                float w = __int_as_float(p.y);
                const __half* s = &g_supporth[(size_t)p.x * FV + lane * VEC];
                if (VEC == 4) {
                    uint2 u = *(const uint2*)s;
                    float2 lo = __half22float2(*(__half2*)&u.x);
                    float2 hi = __half22float2(*(__half2*)&u.y);
                    acc[0] = fmaf(w, lo.x, acc[0]);
                    acc[1] = fmaf(w, lo.y, acc[1]);
                    acc[2] = fmaf(w, hi.x, acc[2]);
                    acc[3] = fmaf(w, hi.y, acc[3]);
                } else {
                    unsigned u = *(const unsigned*)s;
                    float2 lo = __half22float2(*(__half2*)&u);
                    acc[0] = fmaf(w, lo.x, acc[0]);
                    acc[1] = fmaf(w, lo.y, acc[1]);
                }
            };

            int i = beg;
            for (; i + 4 <= end; i += 4) {
                int2 p0 = __ldg(&g_epack[i]);
                int2 p1 = __ldg(&g_epack[i + 1]);
                int2 p2 = __ldg(&g_epack[i + 2]);
                int2 p3 = __ldg(&g_epack[i + 3]);
                gather(p0); gather(p1); gather(p2); gather(p3);
            }
            for (; i < end; i++) gather(__ldg(&g_epack[i]));

#pragma unroll
            for (int v = 0; v < VEC; v++) {
                acc[v] = fmaxf(acc[v] + bv[v], 0.f);
                bsum[v] += acc[v];
            }
            if (HOUT) {
                *(uint2*)&g_xh[(size_t)r * FV + lane * 4] =
                    make_uint2(pack2h(acc[0], acc[1]), pack2h(acc[2], acc[3]));
            } else if (VEC == 4) {
                *(float4*)&g_x[(size_t)r * FV + lane * 4] =
                    make_float4(acc[0], acc[1], acc[2], acc[3]);
            } else {
                *(float2*)&g_x[(size_t)r * FV + lane * 2] =
                    make_float2(acc[0], acc[1]);
            }
        }
#pragma unroll
        for (int v = 0; v < VEC; v++)
            atomicAdd(&cs[lane * VEC + v], bsum[v]);
    }
    __syncthreads();
    if (tid < FV) atomicAdd(&colsum[tid], cs[tid]);
}

// -------- fused PairNorm(F=64) + decode --------
__global__ void decode_pn_kernel(const int* __restrict__ pos, const int* __restrict__ neg,
                                 const float* __restrict__ colsum,
                                 float* __restrict__ out) {
    int gwarp = ((int)blockIdx.x * blockDim.x + threadIdx.x) >> 5;
    int lane = threadIdx.x & 31;
    if (gwarp >= N_EDGES) return;
    const int* ei = (gwarp < 20000) ? (pos + (size_t)gwarp * 2)
                                    : (neg + (size_t)(gwarp - 20000) * 2);
    int a = ei[0];
    int b = ei[1];
    const float invN = 1.0f / N_NODES;
    float m0 = colsum[lane] * invN;
    float m1 = colsum[lane + 32] * invN;
    const float* xa = &g_x[(size_t)a * F_OUTD];
    const float* xb = &g_x[(size_t)b * F_OUTD];
    float va0 = xa[lane] - m0, va1 = xa[lane + 32] - m1;
    float vb0 = xb[lane] - m0, vb1 = xb[lane + 32] - m1;
    float ssa = va0 * va0 + va1 * va1;
    float ssb = vb0 * vb0 + vb1 * vb1;
    float dt  = va0 * vb0 + va1 * vb1;
#pragma unroll
    for (int o = 16; o > 0; o >>= 1) {
        ssa += __shfl_xor_sync(0xffffffffu, ssa, o);
        ssb += __shfl_xor_sync(0xffffffffu, ssb, o);
        dt  += __shfl_xor_sync(0xffffffffu, dt, o);
    }
    if (lane == 0) {
        float s = dt * rsqrtf(EPSV + ssa) * rsqrtf(EPSV + ssb);
        out[gwarp] = 1.0f / (1.0f + expf(-s));
    }
}

// ---------------------------------------------------------------
extern "C" void kernel_launch(void* const* d_in, const int* in_sizes, int n_in,
                              void* d_out, int out_size) {
    const float* in_feature = (const float*)d_in[0];
    const int*   adj_row    = (const int*)d_in[1];
    const int*   adj_col    = (const int*)d_in[2];
    const float* adj_val    = (const float*)d_in[3];
    const int*   pos_ei     = (const int*)d_in[4];
    const int*   neg_ei     = (const int*)d_in[5];
    const float* W0 = (const float*)d_in[6];
    const float* W1 = (const float*)d_in[8];
    const float* W2 = (const float*)d_in[10];
    const float* Bv[3] = { (const float*)d_in[7], (const float*)d_in[9], (const float*)d_in[11] };
    float* out = (float*)d_out;

    __half* d_support = nullptr;
    float* d_colsum = nullptr;
    __half* d_xh = nullptr;
    __half *d_Wh[3];
    cudaGetSymbolAddress((void**)&d_support, g_supporth);
    cudaGetSymbolAddress((void**)&d_colsum, g_colsum3);
    cudaGetSymbolAddress((void**)&d_xh, g_xh);
    cudaGetSymbolAddress((void**)&d_Wh[0], g_W0h);
    cudaGetSymbolAddress((void**)&d_Wh[1], g_W1h);
    cudaGetSymbolAddress((void**)&d_Wh[2], g_W2h);

    cudaFuncSetAttribute((const void*)gemm0_kernel,
                         cudaFuncAttributeMaxDynamicSharedMemorySize, GEMM_SMEM);
    cudaFuncSetAttribute((const void*)gemm_pn_kernel<128>,
                         cudaFuncAttributeMaxDynamicSharedMemorySize, PN_SMEM_128);
    cudaFuncSetAttribute((const void*)gemm_pn_kernel<64>,
                         cudaFuncAttributeMaxDynamicSharedMemorySize, PN_SMEM_64);

    // one-time side stream + events
    static cudaStream_t s2 = nullptr;
    static cudaEvent_t evF = nullptr, evJ = nullptr;
    if (s2 == nullptr) {
        cudaStreamCreateWithFlags(&s2, cudaStreamNonBlocking);
        cudaEventCreateWithFlags(&evF, cudaEventDisableTiming);
        cudaEventCreateWithFlags(&evJ, cudaEventDisableTiming);
    }

    // ---- fork: CSR build on side stream, overlapping prep + GEMM0 ----
    cudaEventRecord(evF, 0);
    cudaStreamWaitEvent(s2, evF, 0);
    csr_zero_kernel<<<(N_NODES + 255) / 256, 256, 0, s2>>>();
    csr_hist_kernel<<<(NNZ + 255) / 256, 256, 0, s2>>>(adj_row);
    csr_scanA_kernel<<<NBLK_SCAN, SCAN_BLK, 0, s2>>>();
    csr_scanB_kernel<<<1, 128, 0, s2>>>();
    csr_scanC_kernel<<<(N_NODES + 255) / 256, 256, 0, s2>>>();
    csr_scatter_kernel<<<(NNZ + 255) / 256, 256, 0, s2>>>(adj_row, adj_col, adj_val);
    cudaEventRecord(evJ, s2);

    // ---- main stream ----
    prep_kernel<<<(PREP_TOTAL + 255) / 256, 256>>>(W0, W1, W2);

    dim3 ggrid(1, (N_NODES + BM - 1) / BM);
    int nwarps = (N_NODES + RPW - 1) / RPW;
    int snblk = (nwarps * 32 + 255) / 256;

    // ---- layer 0 ----
    gemm0_kernel<<<ggrid, 256, GEMM_SMEM>>>(in_feature, d_Wh[0], d_support,
                                            N_NODES, F_IN, KPAD0);
    cudaStreamWaitEvent(0, evJ, 0);   // CSR ready before first SpMM
    spmm_fused_kernel<128, 1><<<snblk, 256>>>(Bv[0], d_colsum + 0 * F_HID);

    // ---- layer 1 (fused pairnorm in GEMM) ----
    gemm_pn_kernel<128><<<ggrid, 256, PN_SMEM_128>>>(d_xh, d_colsum + 0 * F_HID,
                                                     d_Wh[1], d_support, N_NODES, F_HID);
    spmm_fused_kernel<128, 1><<<snblk, 256>>>(Bv[1], d_colsum + 1 * F_HID);

    // ---- layer 2 (fused pairnorm in GEMM, N=64) ----
    gemm_pn_kernel<64><<<ggrid, 256, PN_SMEM_64>>>(d_xh, d_colsum + 1 * F_HID,
                                                   d_Wh[2], d_support, N_NODES, F_OUTD);
    spmm_fused_kernel<64, 0><<<snblk, 256>>>(Bv[2], d_colsum + 2 * F_HID);

    // ---- fused pairnorm64 + decode ----
    int dblocks = (N_EDGES * 32 + 255) / 256;
    decode_pn_kernel<<<dblocks, 256>>>(pos_ei, neg_ei, d_colsum + 2 * F_HID, out);
}